// round 10
// baseline (speedup 1.0000x reference)
#include <cuda_runtime.h>
#include <cstdint>

// ---------------------------------------------------------------------------
// Problem constants
// ---------------------------------------------------------------------------
#define CB   8
#define CN   1024
#define CD   256
#define CH   8
#define CHD  (CH * CD)   // 2048
#define CCAH 4
#define CDH  64

static __device__ __forceinline__ float leaky02(float z) {
    return z >= 0.f ? z : 0.2f * z;
}

// ---------------------------------------------------------------------------
// Scratch (static device globals; no runtime allocation)
// ---------------------------------------------------------------------------
__device__ float g_posq[CB * CD];
__device__ float g_sx[CB * CN * CD];
__device__ float g_qq[CB * CD];
__device__ unsigned char g_sel[CB * CN];
__device__ float g_simtmp[CB * CN];
__device__ float g_fa[CB * CN * CD];
__device__ float g_G[(size_t)CB * CN * CN];                 // also attn_o
__device__ unsigned g_conn[CB * CN * (CN / 32)];
__device__ float g_Wcat[CD * CHD];
__device__ float g_Wh[(size_t)CB * CN * CHD];
__device__ float g_s1[CB * CH * CN];
__device__ float g_s2[CB * CH * CN];
__device__ float g_attn[(size_t)CB * CH * CN * CN];         // also CA logits
__device__ float g_cat[(size_t)CB * CN * CHD];
__device__ float g_Who[CB * CN * CD];
__device__ float g_so1[CB * CN];
__device__ float g_so2[CB * CN];
__device__ float g_gout[CB * CN * CD];
__device__ float g_qx[CB * CN * CD];
__device__ float g_kv[CB * CN * CD];
__device__ float g_q[CB * CN * CD];
__device__ float g_k[CB * CN * CD];
__device__ float g_v[CB * CN * CD];
__device__ float g_o[CB * CN * CD];
__device__ float g_op[CB * CN * CD];

// ---------------------------------------------------------------------------
// TF32x3 tensor-core GEMM: C = alpha * A @ B(^T), fp32-equivalent accuracy.
// Each fp32 input is split a = a_hi + a_lo (both tf32); the product uses
// three mma passes (ah*bh + ah*bl + al*bh), leaving only an O(2^-22)
// residual — the same order as native fp32 rounding.
// Tile 128x128x16, 256 threads (8 warps in 2x4, warp tile 64x32),
// mma.sync.m16n8k8. Batch z -> (b = z/Hh, h = z%Hh) with per-operand strides.
// Requires K % 16 == 0 (true for all call sites: 64/256/1024/2048).
// ---------------------------------------------------------------------------
__device__ __forceinline__ uint32_t f2tf(float f) {
    uint32_t u;
    asm("cvt.rna.tf32.f32 %0, %1;" : "=r"(u) : "f"(f));
    return u;
}

#define MMA_TF32(c, a0, a1, a2, a3, b0, b1)                                   \
    asm volatile("mma.sync.aligned.m16n8k8.row.col.f32.tf32.tf32.f32 "        \
                 "{%0,%1,%2,%3}, {%4,%5,%6,%7}, {%8,%9}, {%0,%1,%2,%3};"      \
                 : "+f"((c)[0]), "+f"((c)[1]), "+f"((c)[2]), "+f"((c)[3])     \
                 : "r"(a0), "r"(a1), "r"(a2), "r"(a3), "r"(b0), "r"(b1))

__global__ void __launch_bounds__(256)
tf32x3_gemm_kernel(const float* __restrict__ A, const float* __restrict__ Bm,
                   float* __restrict__ C,
                   int M, int Nc, int K, int lda, int ldb, int ldc,
                   long long sAb, long long sAh, long long sBb, long long sBh,
                   long long sCb, long long sCh, int Hh, int transB, float alpha)
{
    int z = blockIdx.z;
    int b = z / Hh;
    int h = z - b * Hh;
    A  += (long long)b * sAb + (long long)h * sAh;
    Bm += (long long)b * sBb + (long long)h * sBh;
    C  += (long long)b * sCb + (long long)h * sCh;

    __shared__ uint32_t AsH[128][20], AsL[128][20];
    __shared__ uint32_t BsH[16][136], BsL[16][136];

    int tid  = threadIdx.x;
    int lane = tid & 31, warp = tid >> 5;
    int wr = warp >> 2, wc = warp & 3;       // warp 2x4 layout
    int g = lane >> 2, q = lane & 3;
    int bm0 = blockIdx.y * 128, bn0 = blockIdx.x * 128;

    float acc[4][4][4];
    #pragma unroll
    for (int i = 0; i < 4; i++)
        #pragma unroll
        for (int j = 0; j < 4; j++)
            #pragma unroll
            for (int e = 0; e < 4; e++) acc[i][j][e] = 0.f;

    for (int k0 = 0; k0 < K; k0 += 16) {
        // ---- A tile 128x16 (row-major), float4 loads, tf32 split ----
        #pragma unroll
        for (int i = 0; i < 2; i++) {
            int idx = tid + i * 256;
            int r = idx >> 2, c4 = idx & 3;
            int gr = bm0 + r;
            float4 v = make_float4(0.f, 0.f, 0.f, 0.f);
            if (gr < M) v = *(const float4*)(A + (long long)gr * lda + k0 + c4 * 4);
            float vv[4] = {v.x, v.y, v.z, v.w};
            #pragma unroll
            for (int j = 0; j < 4; j++) {
                uint32_t hi = f2tf(vv[j]);
                uint32_t lo = f2tf(vv[j] - __uint_as_float(hi));
                AsH[r][c4 * 4 + j] = hi;
                AsL[r][c4 * 4 + j] = lo;
            }
        }
        // ---- B tile 16x128 into k-major smem ----
        if (!transB) {
            #pragma unroll
            for (int i = 0; i < 2; i++) {
                int idx = tid + i * 256;
                int k = idx >> 5, c4 = idx & 31;
                int gn = bn0 + c4 * 4;
                float4 v = make_float4(0.f, 0.f, 0.f, 0.f);
                if (gn < Nc) v = *(const float4*)(Bm + (long long)(k0 + k) * ldb + gn);
                float vv[4] = {v.x, v.y, v.z, v.w};
                #pragma unroll
                for (int j = 0; j < 4; j++) {
                    uint32_t hi = f2tf(vv[j]);
                    uint32_t lo = f2tf(vv[j] - __uint_as_float(hi));
                    BsH[k][c4 * 4 + j] = hi;
                    BsL[k][c4 * 4 + j] = lo;
                }
            }
        } else {
            #pragma unroll
            for (int i = 0; i < 2; i++) {
                int idx = tid + i * 256;
                int n = idx >> 2, k4 = idx & 3;
                int gn = bn0 + n;
                float4 v = make_float4(0.f, 0.f, 0.f, 0.f);
                if (gn < Nc) v = *(const float4*)(Bm + (long long)gn * ldb + k0 + k4 * 4);
                float vv[4] = {v.x, v.y, v.z, v.w};
                #pragma unroll
                for (int j = 0; j < 4; j++) {
                    uint32_t hi = f2tf(vv[j]);
                    uint32_t lo = f2tf(vv[j] - __uint_as_float(hi));
                    BsH[k4 * 4 + j][n] = hi;
                    BsL[k4 * 4 + j][n] = lo;
                }
            }
        }
        __syncthreads();

        #pragma unroll
        for (int kk = 0; kk < 16; kk += 8) {
            uint32_t bh_[4][2], bl_[4][2];
            #pragma unroll
            for (int nt = 0; nt < 4; nt++) {
                int n = wc * 32 + nt * 8 + g;
                bh_[nt][0] = BsH[kk + q][n];
                bh_[nt][1] = BsH[kk + q + 4][n];
                bl_[nt][0] = BsL[kk + q][n];
                bl_[nt][1] = BsL[kk + q + 4][n];
            }
            #pragma unroll
            for (int mt = 0; mt < 4; mt++) {
                int m = wr * 64 + mt * 16 + g;
                uint32_t ah0 = AsH[m][kk + q],     ah1 = AsH[m + 8][kk + q];
                uint32_t ah2 = AsH[m][kk + q + 4], ah3 = AsH[m + 8][kk + q + 4];
                uint32_t al0 = AsL[m][kk + q],     al1 = AsL[m + 8][kk + q];
                uint32_t al2 = AsL[m][kk + q + 4], al3 = AsL[m + 8][kk + q + 4];
                #pragma unroll
                for (int nt = 0; nt < 4; nt++) {
                    float* c = acc[mt][nt];
                    MMA_TF32(c, ah0, ah1, ah2, ah3, bl_[nt][0], bl_[nt][1]); // hi*lo
                    MMA_TF32(c, al0, al1, al2, al3, bh_[nt][0], bh_[nt][1]); // lo*hi
                    MMA_TF32(c, ah0, ah1, ah2, ah3, bh_[nt][0], bh_[nt][1]); // hi*hi
                }
            }
        }
        __syncthreads();
    }

    // ---- epilogue: float2 stores ----
    #pragma unroll
    for (int mt = 0; mt < 4; mt++) {
        int r0 = bm0 + wr * 64 + mt * 16 + g;
        #pragma unroll
        for (int nt = 0; nt < 4; nt++) {
            int cix = bn0 + wc * 32 + nt * 8 + q * 2;
            if (cix >= Nc) continue;
            const float* c = acc[mt][nt];
            if (r0 < M)
                *(float2*)(C + (long long)r0 * ldc + cix) =
                    make_float2(alpha * c[0], alpha * c[1]);
            if (r0 + 8 < M)
                *(float2*)(C + (long long)(r0 + 8) * ldc + cix) =
                    make_float2(alpha * c[2], alpha * c[3]);
        }
    }
}

static inline void launch_tgemm(const float* A, const float* Bm, float* C,
                                int M, int Nc, int K, int lda, int ldb, int ldc,
                                long long sAb, long long sAh,
                                long long sBb, long long sBh,
                                long long sCb, long long sCh,
                                int batches, int Hh, int transB, float alpha)
{
    dim3 grid((Nc + 127) / 128, (M + 127) / 128, batches);
    tf32x3_gemm_kernel<<<grid, 256>>>(A, Bm, C, M, Nc, K, lda, ldb, ldc,
                                      sAb, sAh, sBb, sBh, sCb, sCh,
                                      Hh, transB, alpha);
}

static inline void launch_tgemm_plain(const float* A, const float* Bm, float* C,
                                      int M, int Nc, int K,
                                      int lda, int ldb, int ldc)
{
    launch_tgemm(A, Bm, C, M, Nc, K, lda, ldb, ldc, 0, 0, 0, 0, 0, 0, 1, 1, 0, 1.f);
}

// ---------------------------------------------------------------------------
// Small fp32 GEMM (kept only for the tiny 8x256x256 qq projection)
// ---------------------------------------------------------------------------
__global__ void __launch_bounds__(256)
fp32_gemm_small_kernel(const float* __restrict__ A, const float* __restrict__ Bm,
                       float* __restrict__ C, int M, int Nc, int K)
{
    // one warp per output element is overkill; simple: one thread per (m,n)
    int n = blockIdx.x * 256 + threadIdx.x;
    int m = blockIdx.y;
    if (n >= Nc || m >= M) return;
    float s = 0.f;
    for (int k = 0; k < K; k++) s += A[m * K + k] * Bm[k * Nc + n];
    C[m * Nc + n] = s;
}

// ---------------------------------------------------------------------------
// Small fused kernels
// ---------------------------------------------------------------------------
__device__ __forceinline__ float warpSum(float v) {
    #pragma unroll
    for (int o = 16; o; o >>= 1) v += __shfl_down_sync(0xffffffffu, v, o);
    return v;
}

// pos_query: masked mean over N
__global__ void posq_kernel(const float* __restrict__ x, const int* __restrict__ mask,
                            float* __restrict__ pq)
{
    int b = blockIdx.x;
    int t = threadIdx.x;
    const float* xb = x + (size_t)b * CN * CD;
    const int* mb = mask + b * CN;
    float s = 0.f;
    int cnt = 0;
    for (int n = 0; n < CN; n++) {
        if (mb[n] == 1) { s += xb[(size_t)n * CD + t]; cnt++; }
    }
    pq[b * CD + t] = s / fmaxf((float)cnt, 1.f);
}

// pos_sim + sel: one warp per token
__global__ void possim_kernel(const float* __restrict__ sx, const float* __restrict__ qq,
                              float* __restrict__ out_sim, unsigned char* __restrict__ sel)
{
    int gw = (blockIdx.x * blockDim.x + threadIdx.x) >> 5;
    int lane = threadIdx.x & 31;
    if (gw >= CB * CN) return;
    int b = gw >> 10;
    const float* xr = sx + (size_t)gw * CD;
    const float* qr = qq + b * CD;
    float s = 0.f;
    #pragma unroll
    for (int i = lane; i < CD; i += 32) s += xr[i] * qr[i];
    s = warpSum(s);
    if (lane == 0) {
        float ps = 1.f / (1.f + expf(-s * 0.0625f));
        out_sim[gw] = ps;
        sel[gw] = ps > 0.97f ? 1 : 0;
    }
}

// connect bitmask: (fa.fa^T > 0) & sel[n] & sel[m]
__global__ void bitize_kernel(const float* __restrict__ G,
                              const unsigned char* __restrict__ sel,
                              unsigned* __restrict__ conn)
{
    int row = blockIdx.x;               // b*N + n
    int b = row >> 10;
    int lane = threadIdx.x;
    bool seln = sel[row] != 0;
    const float* Gr = G + (size_t)row * CN;
    const unsigned char* sb = sel + b * CN;
    for (int w = 0; w < 32; w++) {
        int m = w * 32 + lane;
        bool bit = seln && (sb[m] != 0) && (Gr[m] > 0.f);
        unsigned word = __ballot_sync(0xffffffffu, bit);
        if (lane == 0) conn[(size_t)row * 32 + w] = word;
    }
}

// permute gat_W [H,d,d] -> Wcat [d, H*d]
__global__ void permW_kernel(const float* __restrict__ W, float* __restrict__ Wc)
{
    int i = blockIdx.x * 256 + threadIdx.x;     // < H*D*D
    int h = i >> 16;
    int r = i & 65535;
    int din = r >> 8;
    int e = r & 255;
    Wc[din * CHD + h * CD + e] = W[i];
}

// s1/s2 = Wh . a1/a2 per (b,h,n). 8 warps/block, warp w = head w.
__global__ void s12_kernel(const float* __restrict__ Wh, const float* __restrict__ a1,
                           const float* __restrict__ a2, float* __restrict__ s1,
                           float* __restrict__ s2)
{
    __shared__ float sa1[CHD], sa2[CHD];
    int t = threadIdx.x;
    for (int i = t; i < CHD; i += 256) { sa1[i] = a1[i]; sa2[i] = a2[i]; }
    __syncthreads();
    int row = blockIdx.x;               // b*N + n
    int w = t >> 5, lane = t & 31;
    const float* wr = Wh + (size_t)row * CHD + w * CD;
    float v1 = 0.f, v2 = 0.f;
    #pragma unroll
    for (int i = lane; i < CD; i += 32) {
        float wv = wr[i];
        v1 += wv * sa1[w * CD + i];
        v2 += wv * sa2[w * CD + i];
    }
    v1 = warpSum(v1);
    v2 = warpSum(v2);
    if (lane == 0) {
        int b = row >> 10, n = row & 1023;
        s1[((size_t)b * CH + w) * CN + n] = v1;
        s2[((size_t)b * CH + w) * CN + n] = v2;
    }
}

// so1/so2: one warp per row
__global__ void so12_kernel(const float* __restrict__ Who, const float* __restrict__ ao1,
                            const float* __restrict__ ao2, float* __restrict__ so1,
                            float* __restrict__ so2)
{
    int gw = (blockIdx.x * blockDim.x + threadIdx.x) >> 5;
    int lane = threadIdx.x & 31;
    if (gw >= CB * CN) return;
    const float* wr = Who + (size_t)gw * CD;
    float v1 = 0.f, v2 = 0.f;
    #pragma unroll
    for (int i = lane; i < CD; i += 32) {
        float w = wr[i];
        v1 += w * ao1[i];
        v2 += w * ao2[i];
    }
    v1 = warpSum(v1);
    v2 = warpSum(v2);
    if (lane == 0) { so1[gw] = v1; so2[gw] = v2; }
}

// Rank-1 masked softmax: logits = conn ? leaky(s1[n]+s2[m]) : -9e15
// blockIdx.x = (b*Hn + h)*N + n ; out row = blockIdx.x * N
__global__ void rank1_softmax_kernel(const float* __restrict__ s1,
                                     const float* __restrict__ s2,
                                     const unsigned* __restrict__ conn,
                                     float* __restrict__ out, int Hn)
{
    int idx = blockIdx.x;
    int n = idx % CN;
    int bh = idx / CN;
    int b = bh / Hn;
    float s1n = s1[idx];
    const float* s2p = s2 + (size_t)bh * CN;
    const unsigned* cw = conn + ((size_t)b * CN + n) * 32;
    int t = threadIdx.x;

    float lg[4];
    #pragma unroll
    for (int i = 0; i < 4; i++) {
        int m = t + i * 256;
        bool c = (cw[m >> 5] >> (m & 31)) & 1u;
        float z = leaky02(s1n + s2p[m]);
        lg[i] = c ? z : -9.0e15f;
    }

    __shared__ float red[256];
    float mx = fmaxf(fmaxf(lg[0], lg[1]), fmaxf(lg[2], lg[3]));
    red[t] = mx; __syncthreads();
    for (int s = 128; s; s >>= 1) { if (t < s) red[t] = fmaxf(red[t], red[t + s]); __syncthreads(); }
    mx = red[0]; __syncthreads();

    float p[4], sm = 0.f;
    #pragma unroll
    for (int i = 0; i < 4; i++) { p[i] = expf(lg[i] - mx); sm += p[i]; }
    red[t] = sm; __syncthreads();
    for (int s = 128; s; s >>= 1) { if (t < s) red[t] += red[t + s]; __syncthreads(); }
    float inv = 1.f / red[0];

    float* orow = out + (size_t)idx * CN;
    #pragma unroll
    for (int i = 0; i < 4; i++) orow[t + i * 256] = p[i] * inv;
}

// CA softmax in-place with key-side sel mask (-1e9). blockIdx.x = (b*4+h)*N + n
__global__ void ca_softmax_kernel(float* __restrict__ logits,
                                  const unsigned char* __restrict__ sel)
{
    int idx = blockIdx.x;
    int b = idx / (CCAH * CN);
    const unsigned char* sb = sel + b * CN;
    float* row = logits + (size_t)idx * CN;
    int t = threadIdx.x;

    float lg[4];
    #pragma unroll
    for (int i = 0; i < 4; i++) {
        int m = t + i * 256;
        lg[i] = sb[m] ? row[m] : -1.0e9f;
    }

    __shared__ float red[256];
    float mx = fmaxf(fmaxf(lg[0], lg[1]), fmaxf(lg[2], lg[3]));
    red[t] = mx; __syncthreads();
    for (int s = 128; s; s >>= 1) { if (t < s) red[t] = fmaxf(red[t], red[t + s]); __syncthreads(); }
    mx = red[0]; __syncthreads();

    float p[4], sm = 0.f;
    #pragma unroll
    for (int i = 0; i < 4; i++) { p[i] = expf(lg[i] - mx); sm += p[i]; }
    red[t] = sm; __syncthreads();
    for (int s = 128; s; s >>= 1) { if (t < s) red[t] += red[t + s]; __syncthreads(); }
    float inv = 1.f / red[0];

    #pragma unroll
    for (int i = 0; i < 4; i++) row[t + i * 256] = p[i] * inv;
}

// LayerNorm: one block (256 threads = D) per row
__global__ void ln_kernel(const float* __restrict__ in, const float* __restrict__ g,
                          const float* __restrict__ bt, float* __restrict__ out)
{
    int row = blockIdx.x;
    int t = threadIdx.x;
    float v = in[(size_t)row * CD + t];
    __shared__ float red[256];
    red[t] = v; __syncthreads();
    for (int s = 128; s; s >>= 1) { if (t < s) red[t] += red[t + s]; __syncthreads(); }
    float mean = red[0] * (1.f / CD);
    __syncthreads();
    float d = v - mean;
    red[t] = d * d; __syncthreads();
    for (int s = 128; s; s >>= 1) { if (t < s) red[t] += red[t + s]; __syncthreads(); }
    float var = red[0] * (1.f / CD);
    out[(size_t)row * CD + t] = d * rsqrtf(var + 1e-5f) * g[t] + bt[t];
}

// kv = LN4( sel ? gout + pe0 : 0 )
__global__ void kv_kernel(const float* __restrict__ gout, const float* __restrict__ pe,
                          const unsigned char* __restrict__ sel,
                          const float* __restrict__ g, const float* __restrict__ bt,
                          float* __restrict__ out)
{
    int row = blockIdx.x;
    int n = row & (CN - 1);
    int t = threadIdx.x;
    float v = sel[row] ? (gout[(size_t)row * CD + t] + pe[(size_t)n * CD + t]) : 0.f;
    __shared__ float red[256];
    red[t] = v; __syncthreads();
    for (int s = 128; s; s >>= 1) { if (t < s) red[t] += red[t + s]; __syncthreads(); }
    float mean = red[0] * (1.f / CD);
    __syncthreads();
    float d = v - mean;
    red[t] = d * d; __syncthreads();
    for (int s = 128; s; s >>= 1) { if (t < s) red[t] += red[t + s]; __syncthreads(); }
    float var = red[0] * (1.f / CD);
    out[(size_t)row * CD + t] = d * rsqrtf(var + 1e-5f) * g[t] + bt[t];
}

__global__ void elu_kernel(float* __restrict__ a, size_t n)
{
    size_t i = (size_t)blockIdx.x * 256 + threadIdx.x;
    if (i < n) {
        float v = a[i];
        a[i] = v > 0.f ? v : expm1f(v);
    }
}

__global__ void final_kernel(const float* __restrict__ x, const float* __restrict__ op,
                             const float* __restrict__ gamma, float* __restrict__ out)
{
    size_t i = (size_t)blockIdx.x * 256 + threadIdx.x;
    float g = gamma[i & 255];
    out[i] = x[i] + g * op[i];
}

// ---------------------------------------------------------------------------
// Launch
// ---------------------------------------------------------------------------
#define SYMADDR(p, s) do { void* _t = nullptr; cudaGetSymbolAddress(&_t, s); p = (decltype(p))_t; } while (0)

extern "C" void kernel_launch(void* const* d_in, const int* in_sizes, int n_in,
                              void* d_out, int out_size)
{
    (void)in_sizes; (void)n_in;
    const float* x      = (const float*)d_in[0];
    const int*   mask   = (const int*)d_in[1];
    const float* pe     = (const float*)d_in[2];
    const float* simWx  = (const float*)d_in[3];
    const float* simWq  = (const float*)d_in[4];
    const float* adjW   = (const float*)d_in[5];
    const float* gatW   = (const float*)d_in[6];
    const float* gata1  = (const float*)d_in[7];
    const float* gata2  = (const float*)d_in[8];
    const float* gatWo  = (const float*)d_in[9];
    const float* gatao1 = (const float*)d_in[10];
    const float* gatao2 = (const float*)d_in[11];
    const float* ln3g   = (const float*)d_in[12];
    const float* ln3b   = (const float*)d_in[13];
    const float* ln4g   = (const float*)d_in[14];
    const float* ln4b   = (const float*)d_in[15];
    const float* caWq   = (const float*)d_in[16];
    const float* caWk   = (const float*)d_in[17];
    const float* caWv   = (const float*)d_in[18];
    const float* caWp   = (const float*)d_in[19];
    const float* gamma  = (const float*)d_in[20];
    float* out = (float*)d_out;

    float *posq, *sx, *qq, *fa, *G, *Wcat, *Wh, *s1, *s2, *attn, *cat, *Who;
    float *so1, *so2, *gout, *qx, *kv, *q, *k, *v, *o, *op, *simtmp;
    unsigned char* sel;
    unsigned* conn;
    SYMADDR(posq, g_posq);   SYMADDR(sx, g_sx);     SYMADDR(qq, g_qq);
    SYMADDR(sel, g_sel);     SYMADDR(simtmp, g_simtmp);
    SYMADDR(fa, g_fa);       SYMADDR(G, g_G);       SYMADDR(conn, g_conn);
    SYMADDR(Wcat, g_Wcat);   SYMADDR(Wh, g_Wh);
    SYMADDR(s1, g_s1);       SYMADDR(s2, g_s2);     SYMADDR(attn, g_attn);
    SYMADDR(cat, g_cat);     SYMADDR(Who, g_Who);
    SYMADDR(so1, g_so1);     SYMADDR(so2, g_so2);   SYMADDR(gout, g_gout);
    SYMADDR(qx, g_qx);       SYMADDR(kv, g_kv);
    SYMADDR(q, g_q);         SYMADDR(k, g_k);       SYMADDR(v, g_v);
    SYMADDR(o, g_o);         SYMADDR(op, g_op);

    const size_t BND = (size_t)CB * CN * CD;
    float* out_sim = (out_size >= (int)(BND + CB * CN)) ? out + BND : simtmp;

    // --- pos_sim / sel -----------------------------------------------------
    posq_kernel<<<CB, CD>>>(x, mask, posq);
    launch_tgemm_plain(x, simWx, sx, CB * CN, CD, CD, CD, CD, CD);
    fp32_gemm_small_kernel<<<dim3(1, CB), 256>>>(posq, simWq, qq, CB, CD, CD);
    possim_kernel<<<(CB * CN) / 8, 256>>>(sx, qq, out_sim, sel);

    // --- adjacency ----------------------------------------------------------
    launch_tgemm_plain(x, adjW, fa, CB * CN, CD, CD, CD, CD, CD);
    launch_tgemm(fa, fa, G, CN, CN, CD, CD, CD, CN,
                 (long long)CN * CD, 0, (long long)CN * CD, 0,
                 (long long)CN * CN, 0, CB, 1, 1, 1.f);
    bitize_kernel<<<CB * CN, 32>>>(G, sel, conn);

    // --- GAT heads ----------------------------------------------------------
    permW_kernel<<<(CH * CD * CD) / 256, 256>>>(gatW, Wcat);
    launch_tgemm_plain(x, Wcat, Wh, CB * CN, CHD, CD, CD, CHD, CHD);
    s12_kernel<<<CB * CN, 256>>>(Wh, gata1, gata2, s1, s2);
    rank1_softmax_kernel<<<CB * CH * CN, 256>>>(s1, s2, conn, attn, CH);
    launch_tgemm(attn, Wh, cat, CN, CD, CN, CN, CHD, CHD,
                 (long long)CH * CN * CN, (long long)CN * CN,
                 (long long)CN * CHD, CD,
                 (long long)CN * CHD, CD, CB * CH, CH, 0, 1.f);
    elu_kernel<<<(unsigned)(((size_t)CB * CN * CHD) / 256), 256>>>(cat, (size_t)CB * CN * CHD);

    // --- GAT output layer ----------------------------------------------------
    launch_tgemm_plain(cat, gatWo, Who, CB * CN, CD, CHD, CHD, CD, CD);
    so12_kernel<<<(CB * CN) / 8, 256>>>(Who, gatao1, gatao2, so1, so2);
    rank1_softmax_kernel<<<CB * CN, 256>>>(so1, so2, conn, G, 1);
    launch_tgemm(G, Who, gout, CN, CD, CN, CN, CD, CD,
                 (long long)CN * CN, 0, (long long)CN * CD, 0,
                 (long long)CN * CD, 0, CB, 1, 0, 1.f);
    elu_kernel<<<(unsigned)(BND / 256), 256>>>(gout, BND);

    // --- CrossAttention -------------------------------------------------------
    ln_kernel<<<CB * CN, 256>>>(x, ln3g, ln3b, qx);
    kv_kernel<<<CB * CN, 256>>>(gout, pe, sel, ln4g, ln4b, kv);
    launch_tgemm_plain(qx, caWq, q, CB * CN, CD, CD, CD, CD, CD);
    launch_tgemm_plain(kv, caWk, k, CB * CN, CD, CD, CD, CD, CD);
    launch_tgemm_plain(kv, caWv, v, CB * CN, CD, CD, CD, CD, CD);
    launch_tgemm(q, k, attn, CN, CN, CDH, CD, CD, CN,
                 (long long)CN * CD, CDH, (long long)CN * CD, CDH,
                 (long long)CCAH * CN * CN, (long long)CN * CN,
                 CB * CCAH, CCAH, 1, 0.125f);
    ca_softmax_kernel<<<CB * CCAH * CN, 256>>>(attn, sel);
    launch_tgemm(attn, v, o, CN, CDH, CN, CN, CD, CD,
                 (long long)CCAH * CN * CN, (long long)CN * CN,
                 (long long)CN * CD, CDH,
                 (long long)CN * CD, CDH, CB * CCAH, CCAH, 0, 1.f);
    launch_tgemm_plain(o, caWp, op, CB * CN, CD, CD, CD, CD, CD);

    final_kernel<<<(unsigned)(BND / 256), 256>>>(x, op, gamma, out);
}

// round 11
// speedup vs baseline: 1.0056x; 1.0056x over previous
#include <cuda_runtime.h>
#include <cstdint>

// ---------------------------------------------------------------------------
// Problem constants
// ---------------------------------------------------------------------------
#define CB   8
#define CN   1024
#define CD   256
#define CH   8
#define CHD  (CH * CD)   // 2048
#define CCAH 4
#define CDH  64

static __device__ __forceinline__ float leaky02(float z) {
    return z >= 0.f ? z : 0.2f * z;
}

// ---------------------------------------------------------------------------
// Scratch (static device globals; no runtime allocation)
// ---------------------------------------------------------------------------
__device__ float g_posq[CB * CD];
__device__ float g_sx[CB * CN * CD];
__device__ float g_qq[CB * CD];
__device__ unsigned char g_sel[CB * CN];
__device__ float g_simtmp[CB * CN];
__device__ float g_fa[CB * CN * CD];
__device__ float g_G[(size_t)CB * CN * CN];                 // also attn_o
__device__ unsigned g_conn[CB * CN * (CN / 32)];
__device__ float g_Wcat[CD * CHD];
__device__ float g_Wh[(size_t)CB * CN * CHD];
__device__ float g_s1[CB * CH * CN];
__device__ float g_s2[CB * CH * CN];
__device__ float g_attn[(size_t)CB * CH * CN * CN];         // also CA logits
__device__ float g_cat[(size_t)CB * CN * CHD];
__device__ float g_Who[CB * CN * CD];
__device__ float g_so1[CB * CN];
__device__ float g_so2[CB * CN];
__device__ float g_gout[CB * CN * CD];
__device__ float g_qx[CB * CN * CD];
__device__ float g_kv[CB * CN * CD];
__device__ float g_q[CB * CN * CD];
__device__ float g_k[CB * CN * CD];
__device__ float g_v[CB * CN * CD];
__device__ float g_o[CB * CN * CD];
__device__ float g_op[CB * CN * CD];

// ---------------------------------------------------------------------------
// TF32x3 tensor-core GEMM: C = alpha * A @ B(^T), fp32-equivalent accuracy.
// Each fp32 input is split a = a_hi + a_lo (both tf32); the product uses
// three mma passes (ah*bh + ah*bl + al*bh), leaving only an O(2^-22)
// residual — the same order as native fp32 rounding.
// Tile 128x128x16, 256 threads (8 warps in 2x4, warp tile 64x32),
// mma.sync.m16n8k8. Batch z -> (b = z/Hh, h = z%Hh) with per-operand strides.
// Requires K % 16 == 0 (true for all call sites: 64/256/1024/2048).
// ---------------------------------------------------------------------------
__device__ __forceinline__ uint32_t f2tf(float f) {
    uint32_t u;
    asm("cvt.rna.tf32.f32 %0, %1;" : "=r"(u) : "f"(f));
    return u;
}

#define MMA_TF32(c, a0, a1, a2, a3, b0, b1)                                   \
    asm volatile("mma.sync.aligned.m16n8k8.row.col.f32.tf32.tf32.f32 "        \
                 "{%0,%1,%2,%3}, {%4,%5,%6,%7}, {%8,%9}, {%0,%1,%2,%3};"      \
                 : "+f"((c)[0]), "+f"((c)[1]), "+f"((c)[2]), "+f"((c)[3])     \
                 : "r"(a0), "r"(a1), "r"(a2), "r"(a3), "r"(b0), "r"(b1))

__global__ void __launch_bounds__(256)
tf32x3_gemm_kernel(const float* __restrict__ A, const float* __restrict__ Bm,
                   float* __restrict__ C,
                   int M, int Nc, int K, int lda, int ldb, int ldc,
                   long long sAb, long long sAh, long long sBb, long long sBh,
                   long long sCb, long long sCh, int Hh, int transB, float alpha)
{
    int z = blockIdx.z;
    int b = z / Hh;
    int h = z - b * Hh;
    A  += (long long)b * sAb + (long long)h * sAh;
    Bm += (long long)b * sBb + (long long)h * sBh;
    C  += (long long)b * sCb + (long long)h * sCh;

    __shared__ uint32_t AsH[128][20], AsL[128][20];
    __shared__ uint32_t BsH[16][136], BsL[16][136];

    int tid  = threadIdx.x;
    int lane = tid & 31, warp = tid >> 5;
    int wr = warp >> 2, wc = warp & 3;       // warp 2x4 layout
    int g = lane >> 2, q = lane & 3;
    int bm0 = blockIdx.y * 128, bn0 = blockIdx.x * 128;

    float acc[4][4][4];
    #pragma unroll
    for (int i = 0; i < 4; i++)
        #pragma unroll
        for (int j = 0; j < 4; j++)
            #pragma unroll
            for (int e = 0; e < 4; e++) acc[i][j][e] = 0.f;

    for (int k0 = 0; k0 < K; k0 += 16) {
        // ---- A tile 128x16 (row-major), float4 loads, tf32 split ----
        #pragma unroll
        for (int i = 0; i < 2; i++) {
            int idx = tid + i * 256;
            int r = idx >> 2, c4 = idx & 3;
            int gr = bm0 + r;
            float4 v = make_float4(0.f, 0.f, 0.f, 0.f);
            if (gr < M) v = *(const float4*)(A + (long long)gr * lda + k0 + c4 * 4);
            float vv[4] = {v.x, v.y, v.z, v.w};
            #pragma unroll
            for (int j = 0; j < 4; j++) {
                uint32_t hi = f2tf(vv[j]);
                uint32_t lo = f2tf(vv[j] - __uint_as_float(hi));
                AsH[r][c4 * 4 + j] = hi;
                AsL[r][c4 * 4 + j] = lo;
            }
        }
        // ---- B tile 16x128 into k-major smem ----
        if (!transB) {
            #pragma unroll
            for (int i = 0; i < 2; i++) {
                int idx = tid + i * 256;
                int k = idx >> 5, c4 = idx & 31;
                int gn = bn0 + c4 * 4;
                float4 v = make_float4(0.f, 0.f, 0.f, 0.f);
                if (gn < Nc) v = *(const float4*)(Bm + (long long)(k0 + k) * ldb + gn);
                float vv[4] = {v.x, v.y, v.z, v.w};
                #pragma unroll
                for (int j = 0; j < 4; j++) {
                    uint32_t hi = f2tf(vv[j]);
                    uint32_t lo = f2tf(vv[j] - __uint_as_float(hi));
                    BsH[k][c4 * 4 + j] = hi;
                    BsL[k][c4 * 4 + j] = lo;
                }
            }
        } else {
            #pragma unroll
            for (int i = 0; i < 2; i++) {
                int idx = tid + i * 256;
                int n = idx >> 2, k4 = idx & 3;
                int gn = bn0 + n;
                float4 v = make_float4(0.f, 0.f, 0.f, 0.f);
                if (gn < Nc) v = *(const float4*)(Bm + (long long)gn * ldb + k0 + k4 * 4);
                float vv[4] = {v.x, v.y, v.z, v.w};
                #pragma unroll
                for (int j = 0; j < 4; j++) {
                    uint32_t hi = f2tf(vv[j]);
                    uint32_t lo = f2tf(vv[j] - __uint_as_float(hi));
                    BsH[k4 * 4 + j][n] = hi;
                    BsL[k4 * 4 + j][n] = lo;
                }
            }
        }
        __syncthreads();

        #pragma unroll
        for (int kk = 0; kk < 16; kk += 8) {
            uint32_t bh_[4][2], bl_[4][2];
            #pragma unroll
            for (int nt = 0; nt < 4; nt++) {
                int n = wc * 32 + nt * 8 + g;
                bh_[nt][0] = BsH[kk + q][n];
                bh_[nt][1] = BsH[kk + q + 4][n];
                bl_[nt][0] = BsL[kk + q][n];
                bl_[nt][1] = BsL[kk + q + 4][n];
            }
            #pragma unroll
            for (int mt = 0; mt < 4; mt++) {
                int m = wr * 64 + mt * 16 + g;
                uint32_t ah0 = AsH[m][kk + q],     ah1 = AsH[m + 8][kk + q];
                uint32_t ah2 = AsH[m][kk + q + 4], ah3 = AsH[m + 8][kk + q + 4];
                uint32_t al0 = AsL[m][kk + q],     al1 = AsL[m + 8][kk + q];
                uint32_t al2 = AsL[m][kk + q + 4], al3 = AsL[m + 8][kk + q + 4];
                #pragma unroll
                for (int nt = 0; nt < 4; nt++) {
                    float* c = acc[mt][nt];
                    MMA_TF32(c, ah0, ah1, ah2, ah3, bl_[nt][0], bl_[nt][1]); // hi*lo
                    MMA_TF32(c, al0, al1, al2, al3, bh_[nt][0], bh_[nt][1]); // lo*hi
                    MMA_TF32(c, ah0, ah1, ah2, ah3, bh_[nt][0], bh_[nt][1]); // hi*hi
                }
            }
        }
        __syncthreads();
    }

    // ---- epilogue: float2 stores ----
    #pragma unroll
    for (int mt = 0; mt < 4; mt++) {
        int r0 = bm0 + wr * 64 + mt * 16 + g;
        #pragma unroll
        for (int nt = 0; nt < 4; nt++) {
            int cix = bn0 + wc * 32 + nt * 8 + q * 2;
            if (cix >= Nc) continue;
            const float* c = acc[mt][nt];
            if (r0 < M)
                *(float2*)(C + (long long)r0 * ldc + cix) =
                    make_float2(alpha * c[0], alpha * c[1]);
            if (r0 + 8 < M)
                *(float2*)(C + (long long)(r0 + 8) * ldc + cix) =
                    make_float2(alpha * c[2], alpha * c[3]);
        }
    }
}

static inline void launch_tgemm(const float* A, const float* Bm, float* C,
                                int M, int Nc, int K, int lda, int ldb, int ldc,
                                long long sAb, long long sAh,
                                long long sBb, long long sBh,
                                long long sCb, long long sCh,
                                int batches, int Hh, int transB, float alpha)
{
    dim3 grid((Nc + 127) / 128, (M + 127) / 128, batches);
    tf32x3_gemm_kernel<<<grid, 256>>>(A, Bm, C, M, Nc, K, lda, ldb, ldc,
                                      sAb, sAh, sBb, sBh, sCb, sCh,
                                      Hh, transB, alpha);
}

static inline void launch_tgemm_plain(const float* A, const float* Bm, float* C,
                                      int M, int Nc, int K,
                                      int lda, int ldb, int ldc)
{
    launch_tgemm(A, Bm, C, M, Nc, K, lda, ldb, ldc, 0, 0, 0, 0, 0, 0, 1, 1, 0, 1.f);
}

// ---------------------------------------------------------------------------
// Small fp32 GEMM (kept only for the tiny 8x256x256 qq projection)
// ---------------------------------------------------------------------------
__global__ void __launch_bounds__(256)
fp32_gemm_small_kernel(const float* __restrict__ A, const float* __restrict__ Bm,
                       float* __restrict__ C, int M, int Nc, int K)
{
    // one warp per output element is overkill; simple: one thread per (m,n)
    int n = blockIdx.x * 256 + threadIdx.x;
    int m = blockIdx.y;
    if (n >= Nc || m >= M) return;
    float s = 0.f;
    for (int k = 0; k < K; k++) s += A[m * K + k] * Bm[k * Nc + n];
    C[m * Nc + n] = s;
}

// ---------------------------------------------------------------------------
// Small fused kernels
// ---------------------------------------------------------------------------
__device__ __forceinline__ float warpSum(float v) {
    #pragma unroll
    for (int o = 16; o; o >>= 1) v += __shfl_down_sync(0xffffffffu, v, o);
    return v;
}

// pos_query: masked mean over N
__global__ void posq_kernel(const float* __restrict__ x, const int* __restrict__ mask,
                            float* __restrict__ pq)
{
    int b = blockIdx.x;
    int t = threadIdx.x;
    const float* xb = x + (size_t)b * CN * CD;
    const int* mb = mask + b * CN;
    float s = 0.f;
    int cnt = 0;
    for (int n = 0; n < CN; n++) {
        if (mb[n] == 1) { s += xb[(size_t)n * CD + t]; cnt++; }
    }
    pq[b * CD + t] = s / fmaxf((float)cnt, 1.f);
}

// pos_sim + sel: one warp per token
__global__ void possim_kernel(const float* __restrict__ sx, const float* __restrict__ qq,
                              float* __restrict__ out_sim, unsigned char* __restrict__ sel)
{
    int gw = (blockIdx.x * blockDim.x + threadIdx.x) >> 5;
    int lane = threadIdx.x & 31;
    if (gw >= CB * CN) return;
    int b = gw >> 10;
    const float* xr = sx + (size_t)gw * CD;
    const float* qr = qq + b * CD;
    float s = 0.f;
    #pragma unroll
    for (int i = lane; i < CD; i += 32) s += xr[i] * qr[i];
    s = warpSum(s);
    if (lane == 0) {
        float ps = 1.f / (1.f + expf(-s * 0.0625f));
        out_sim[gw] = ps;
        sel[gw] = ps > 0.97f ? 1 : 0;
    }
}

// connect bitmask: (fa.fa^T > 0) & sel[n] & sel[m]
__global__ void bitize_kernel(const float* __restrict__ G,
                              const unsigned char* __restrict__ sel,
                              unsigned* __restrict__ conn)
{
    int row = blockIdx.x;               // b*N + n
    int b = row >> 10;
    int lane = threadIdx.x;
    bool seln = sel[row] != 0;
    const float* Gr = G + (size_t)row * CN;
    const unsigned char* sb = sel + b * CN;
    for (int w = 0; w < 32; w++) {
        int m = w * 32 + lane;
        bool bit = seln && (sb[m] != 0) && (Gr[m] > 0.f);
        unsigned word = __ballot_sync(0xffffffffu, bit);
        if (lane == 0) conn[(size_t)row * 32 + w] = word;
    }
}

// permute gat_W [H,d,d] -> Wcat [d, H*d]
__global__ void permW_kernel(const float* __restrict__ W, float* __restrict__ Wc)
{
    int i = blockIdx.x * 256 + threadIdx.x;     // < H*D*D
    int h = i >> 16;
    int r = i & 65535;
    int din = r >> 8;
    int e = r & 255;
    Wc[din * CHD + h * CD + e] = W[i];
}

// s1/s2 = Wh . a1/a2 per (b,h,n). 8 warps/block, warp w = head w.
__global__ void s12_kernel(const float* __restrict__ Wh, const float* __restrict__ a1,
                           const float* __restrict__ a2, float* __restrict__ s1,
                           float* __restrict__ s2)
{
    __shared__ float sa1[CHD], sa2[CHD];
    int t = threadIdx.x;
    for (int i = t; i < CHD; i += 256) { sa1[i] = a1[i]; sa2[i] = a2[i]; }
    __syncthreads();
    int row = blockIdx.x;               // b*N + n
    int w = t >> 5, lane = t & 31;
    const float* wr = Wh + (size_t)row * CHD + w * CD;
    float v1 = 0.f, v2 = 0.f;
    #pragma unroll
    for (int i = lane; i < CD; i += 32) {
        float wv = wr[i];
        v1 += wv * sa1[w * CD + i];
        v2 += wv * sa2[w * CD + i];
    }
    v1 = warpSum(v1);
    v2 = warpSum(v2);
    if (lane == 0) {
        int b = row >> 10, n = row & 1023;
        s1[((size_t)b * CH + w) * CN + n] = v1;
        s2[((size_t)b * CH + w) * CN + n] = v2;
    }
}

// so1/so2: one warp per row
__global__ void so12_kernel(const float* __restrict__ Who, const float* __restrict__ ao1,
                            const float* __restrict__ ao2, float* __restrict__ so1,
                            float* __restrict__ so2)
{
    int gw = (blockIdx.x * blockDim.x + threadIdx.x) >> 5;
    int lane = threadIdx.x & 31;
    if (gw >= CB * CN) return;
    const float* wr = Who + (size_t)gw * CD;
    float v1 = 0.f, v2 = 0.f;
    #pragma unroll
    for (int i = lane; i < CD; i += 32) {
        float w = wr[i];
        v1 += w * ao1[i];
        v2 += w * ao2[i];
    }
    v1 = warpSum(v1);
    v2 = warpSum(v2);
    if (lane == 0) { so1[gw] = v1; so2[gw] = v2; }
}

// Rank-1 masked softmax: logits = conn ? leaky(s1[n]+s2[m]) : -9e15
// blockIdx.x = (b*Hn + h)*N + n ; out row = blockIdx.x * N
__global__ void rank1_softmax_kernel(const float* __restrict__ s1,
                                     const float* __restrict__ s2,
                                     const unsigned* __restrict__ conn,
                                     float* __restrict__ out, int Hn)
{
    int idx = blockIdx.x;
    int n = idx % CN;
    int bh = idx / CN;
    int b = bh / Hn;
    float s1n = s1[idx];
    const float* s2p = s2 + (size_t)bh * CN;
    const unsigned* cw = conn + ((size_t)b * CN + n) * 32;
    int t = threadIdx.x;

    float lg[4];
    #pragma unroll
    for (int i = 0; i < 4; i++) {
        int m = t + i * 256;
        bool c = (cw[m >> 5] >> (m & 31)) & 1u;
        float z = leaky02(s1n + s2p[m]);
        lg[i] = c ? z : -9.0e15f;
    }

    __shared__ float red[256];
    float mx = fmaxf(fmaxf(lg[0], lg[1]), fmaxf(lg[2], lg[3]));
    red[t] = mx; __syncthreads();
    for (int s = 128; s; s >>= 1) { if (t < s) red[t] = fmaxf(red[t], red[t + s]); __syncthreads(); }
    mx = red[0]; __syncthreads();

    float p[4], sm = 0.f;
    #pragma unroll
    for (int i = 0; i < 4; i++) { p[i] = expf(lg[i] - mx); sm += p[i]; }
    red[t] = sm; __syncthreads();
    for (int s = 128; s; s >>= 1) { if (t < s) red[t] += red[t + s]; __syncthreads(); }
    float inv = 1.f / red[0];

    float* orow = out + (size_t)idx * CN;
    #pragma unroll
    for (int i = 0; i < 4; i++) orow[t + i * 256] = p[i] * inv;
}

// CA softmax in-place with key-side sel mask (-1e9). blockIdx.x = (b*4+h)*N + n
__global__ void ca_softmax_kernel(float* __restrict__ logits,
                                  const unsigned char* __restrict__ sel)
{
    int idx = blockIdx.x;
    int b = idx / (CCAH * CN);
    const unsigned char* sb = sel + b * CN;
    float* row = logits + (size_t)idx * CN;
    int t = threadIdx.x;

    float lg[4];
    #pragma unroll
    for (int i = 0; i < 4; i++) {
        int m = t + i * 256;
        lg[i] = sb[m] ? row[m] : -1.0e9f;
    }

    __shared__ float red[256];
    float mx = fmaxf(fmaxf(lg[0], lg[1]), fmaxf(lg[2], lg[3]));
    red[t] = mx; __syncthreads();
    for (int s = 128; s; s >>= 1) { if (t < s) red[t] = fmaxf(red[t], red[t + s]); __syncthreads(); }
    mx = red[0]; __syncthreads();

    float p[4], sm = 0.f;
    #pragma unroll
    for (int i = 0; i < 4; i++) { p[i] = expf(lg[i] - mx); sm += p[i]; }
    red[t] = sm; __syncthreads();
    for (int s = 128; s; s >>= 1) { if (t < s) red[t] += red[t + s]; __syncthreads(); }
    float inv = 1.f / red[0];

    #pragma unroll
    for (int i = 0; i < 4; i++) row[t + i * 256] = p[i] * inv;
}

// LayerNorm: one block (256 threads = D) per row
__global__ void ln_kernel(const float* __restrict__ in, const float* __restrict__ g,
                          const float* __restrict__ bt, float* __restrict__ out)
{
    int row = blockIdx.x;
    int t = threadIdx.x;
    float v = in[(size_t)row * CD + t];
    __shared__ float red[256];
    red[t] = v; __syncthreads();
    for (int s = 128; s; s >>= 1) { if (t < s) red[t] += red[t + s]; __syncthreads(); }
    float mean = red[0] * (1.f / CD);
    __syncthreads();
    float d = v - mean;
    red[t] = d * d; __syncthreads();
    for (int s = 128; s; s >>= 1) { if (t < s) red[t] += red[t + s]; __syncthreads(); }
    float var = red[0] * (1.f / CD);
    out[(size_t)row * CD + t] = d * rsqrtf(var + 1e-5f) * g[t] + bt[t];
}

// kv = LN4( sel ? gout + pe0 : 0 )
__global__ void kv_kernel(const float* __restrict__ gout, const float* __restrict__ pe,
                          const unsigned char* __restrict__ sel,
                          const float* __restrict__ g, const float* __restrict__ bt,
                          float* __restrict__ out)
{
    int row = blockIdx.x;
    int n = row & (CN - 1);
    int t = threadIdx.x;
    float v = sel[row] ? (gout[(size_t)row * CD + t] + pe[(size_t)n * CD + t]) : 0.f;
    __shared__ float red[256];
    red[t] = v; __syncthreads();
    for (int s = 128; s; s >>= 1) { if (t < s) red[t] += red[t + s]; __syncthreads(); }
    float mean = red[0] * (1.f / CD);
    __syncthreads();
    float d = v - mean;
    red[t] = d * d; __syncthreads();
    for (int s = 128; s; s >>= 1) { if (t < s) red[t] += red[t + s]; __syncthreads(); }
    float var = red[0] * (1.f / CD);
    out[(size_t)row * CD + t] = d * rsqrtf(var + 1e-5f) * g[t] + bt[t];
}

__global__ void elu_kernel(float* __restrict__ a, size_t n)
{
    size_t i = (size_t)blockIdx.x * 256 + threadIdx.x;
    if (i < n) {
        float v = a[i];
        a[i] = v > 0.f ? v : expm1f(v);
    }
}

__global__ void final_kernel(const float* __restrict__ x, const float* __restrict__ op,
                             const float* __restrict__ gamma, float* __restrict__ out)
{
    size_t i = (size_t)blockIdx.x * 256 + threadIdx.x;
    float g = gamma[i & 255];
    out[i] = x[i] + g * op[i];
}

// ---------------------------------------------------------------------------
// Launch
// ---------------------------------------------------------------------------
#define SYMADDR(p, s) do { void* _t = nullptr; cudaGetSymbolAddress(&_t, s); p = (decltype(p))_t; } while (0)

extern "C" void kernel_launch(void* const* d_in, const int* in_sizes, int n_in,
                              void* d_out, int out_size)
{
    (void)in_sizes; (void)n_in;
    const float* x      = (const float*)d_in[0];
    const int*   mask   = (const int*)d_in[1];
    const float* pe     = (const float*)d_in[2];
    const float* simWx  = (const float*)d_in[3];
    const float* simWq  = (const float*)d_in[4];
    const float* adjW   = (const float*)d_in[5];
    const float* gatW   = (const float*)d_in[6];
    const float* gata1  = (const float*)d_in[7];
    const float* gata2  = (const float*)d_in[8];
    const float* gatWo  = (const float*)d_in[9];
    const float* gatao1 = (const float*)d_in[10];
    const float* gatao2 = (const float*)d_in[11];
    const float* ln3g   = (const float*)d_in[12];
    const float* ln3b   = (const float*)d_in[13];
    const float* ln4g   = (const float*)d_in[14];
    const float* ln4b   = (const float*)d_in[15];
    const float* caWq   = (const float*)d_in[16];
    const float* caWk   = (const float*)d_in[17];
    const float* caWv   = (const float*)d_in[18];
    const float* caWp   = (const float*)d_in[19];
    const float* gamma  = (const float*)d_in[20];
    float* out = (float*)d_out;

    float *posq, *sx, *qq, *fa, *G, *Wcat, *Wh, *s1, *s2, *attn, *cat, *Who;
    float *so1, *so2, *gout, *qx, *kv, *q, *k, *v, *o, *op, *simtmp;
    unsigned char* sel;
    unsigned* conn;
    SYMADDR(posq, g_posq);   SYMADDR(sx, g_sx);     SYMADDR(qq, g_qq);
    SYMADDR(sel, g_sel);     SYMADDR(simtmp, g_simtmp);
    SYMADDR(fa, g_fa);       SYMADDR(G, g_G);       SYMADDR(conn, g_conn);
    SYMADDR(Wcat, g_Wcat);   SYMADDR(Wh, g_Wh);
    SYMADDR(s1, g_s1);       SYMADDR(s2, g_s2);     SYMADDR(attn, g_attn);
    SYMADDR(cat, g_cat);     SYMADDR(Who, g_Who);
    SYMADDR(so1, g_so1);     SYMADDR(so2, g_so2);   SYMADDR(gout, g_gout);
    SYMADDR(qx, g_qx);       SYMADDR(kv, g_kv);
    SYMADDR(q, g_q);         SYMADDR(k, g_k);       SYMADDR(v, g_v);
    SYMADDR(o, g_o);         SYMADDR(op, g_op);

    const size_t BND = (size_t)CB * CN * CD;
    float* out_sim = (out_size >= (int)(BND + CB * CN)) ? out + BND : simtmp;

    // --- pos_sim / sel -----------------------------------------------------
    posq_kernel<<<CB, CD>>>(x, mask, posq);
    launch_tgemm_plain(x, simWx, sx, CB * CN, CD, CD, CD, CD, CD);
    fp32_gemm_small_kernel<<<dim3(1, CB), 256>>>(posq, simWq, qq, CB, CD, CD);
    possim_kernel<<<(CB * CN) / 8, 256>>>(sx, qq, out_sim, sel);

    // --- adjacency ----------------------------------------------------------
    launch_tgemm_plain(x, adjW, fa, CB * CN, CD, CD, CD, CD, CD);
    launch_tgemm(fa, fa, G, CN, CN, CD, CD, CD, CN,
                 (long long)CN * CD, 0, (long long)CN * CD, 0,
                 (long long)CN * CN, 0, CB, 1, 1, 1.f);
    bitize_kernel<<<CB * CN, 32>>>(G, sel, conn);

    // --- GAT heads ----------------------------------------------------------
    permW_kernel<<<(CH * CD * CD) / 256, 256>>>(gatW, Wcat);
    launch_tgemm_plain(x, Wcat, Wh, CB * CN, CHD, CD, CD, CHD, CHD);
    s12_kernel<<<CB * CN, 256>>>(Wh, gata1, gata2, s1, s2);
    rank1_softmax_kernel<<<CB * CH * CN, 256>>>(s1, s2, conn, attn, CH);
    launch_tgemm(attn, Wh, cat, CN, CD, CN, CN, CHD, CHD,
                 (long long)CH * CN * CN, (long long)CN * CN,
                 (long long)CN * CHD, CD,
                 (long long)CN * CHD, CD, CB * CH, CH, 0, 1.f);
    elu_kernel<<<(unsigned)(((size_t)CB * CN * CHD) / 256), 256>>>(cat, (size_t)CB * CN * CHD);

    // --- GAT output layer ----------------------------------------------------
    launch_tgemm_plain(cat, gatWo, Who, CB * CN, CD, CHD, CHD, CD, CD);
    so12_kernel<<<(CB * CN) / 8, 256>>>(Who, gatao1, gatao2, so1, so2);
    rank1_softmax_kernel<<<CB * CN, 256>>>(so1, so2, conn, G, 1);
    launch_tgemm(G, Who, gout, CN, CD, CN, CN, CD, CD,
                 (long long)CN * CN, 0, (long long)CN * CD, 0,
                 (long long)CN * CD, 0, CB, 1, 0, 1.f);
    elu_kernel<<<(unsigned)(BND / 256), 256>>>(gout, BND);

    // --- CrossAttention -------------------------------------------------------
    ln_kernel<<<CB * CN, 256>>>(x, ln3g, ln3b, qx);
    kv_kernel<<<CB * CN, 256>>>(gout, pe, sel, ln4g, ln4b, kv);
    launch_tgemm_plain(qx, caWq, q, CB * CN, CD, CD, CD, CD, CD);
    launch_tgemm_plain(kv, caWk, k, CB * CN, CD, CD, CD, CD, CD);
    launch_tgemm_plain(kv, caWv, v, CB * CN, CD, CD, CD, CD, CD);
    launch_tgemm(q, k, attn, CN, CN, CDH, CD, CD, CN,
                 (long long)CN * CD, CDH, (long long)CN * CD, CDH,
                 (long long)CCAH * CN * CN, (long long)CN * CN,
                 CB * CCAH, CCAH, 1, 0.125f);
    ca_softmax_kernel<<<CB * CCAH * CN, 256>>>(attn, sel);
    launch_tgemm(attn, v, o, CN, CDH, CN, CN, CD, CD,
                 (long long)CCAH * CN * CN, (long long)CN * CN,
                 (long long)CN * CD, CDH,
                 (long long)CN * CD, CDH, CB * CCAH, CCAH, 0, 1.f);
    launch_tgemm_plain(o, caWp, op, CB * CN, CD, CD, CD, CD, CD);

    final_kernel<<<(unsigned)(BND / 256), 256>>>(x, op, gamma, out);
}

// round 12
// speedup vs baseline: 1.1722x; 1.1657x over previous
#include <cuda_runtime.h>
#include <cstdint>

// ---------------------------------------------------------------------------
// Problem constants
// ---------------------------------------------------------------------------
#define CB   8
#define CN   1024
#define CD   256
#define CH   8
#define CHD  (CH * CD)   // 2048
#define CCAH 4
#define CDH  64

static __device__ __forceinline__ float leaky02(float z) {
    return z >= 0.f ? z : 0.2f * z;
}

// ---------------------------------------------------------------------------
// Scratch (static device globals; no runtime allocation)
// ---------------------------------------------------------------------------
__device__ float g_posq[CB * CD];
__device__ float g_sx[CB * CN * CD];
__device__ float g_qq[CB * CD];
__device__ unsigned char g_sel[CB * CN];
__device__ float g_simtmp[CB * CN];
__device__ float g_fa[CB * CN * CD];
__device__ float g_G[(size_t)CB * CN * CN];                 // also attn_o
__device__ unsigned g_conn[CB * CN * (CN / 32)];
__device__ float g_Wcat[CD * CHD];
__device__ float g_Wh[(size_t)CB * CN * CHD];
__device__ float g_s1[CB * CH * CN];
__device__ float g_s2[CB * CH * CN];
__device__ float g_attn[(size_t)CB * CH * CN * CN];         // also CA logits
__device__ float g_cat[(size_t)CB * CN * CHD];
__device__ float g_Who[CB * CN * CD];
__device__ float g_so1[CB * CN];
__device__ float g_so2[CB * CN];
__device__ float g_gout[CB * CN * CD];
__device__ float g_qx[CB * CN * CD];
__device__ float g_kv[CB * CN * CD];
__device__ float g_q[CB * CN * CD];
__device__ float g_k[CB * CN * CD];
__device__ float g_v[CB * CN * CD];
__device__ float g_o[CB * CN * CD];
__device__ float g_op[CB * CN * CD];

// ---------------------------------------------------------------------------
// TF32x3 tensor-core GEMM (pipelined): C = alpha * A @ B(^T).
// fp32 inputs split a = a_hi + a_lo (tf32 each); 3 mma passes per product.
// Tile 128x128x16, 256 threads (8 warps 2x4, warp tile 64x32), m16n8k8.
// smem holds (hi,lo) interleaved uint2 with XOR swizzle -> conflict-free
// LDS.64 fragment loads. 2-stage double buffering with register staging.
// Requires K % 16 == 0 and M % 128 == 0 at call sites (true everywhere).
// ---------------------------------------------------------------------------
__device__ __forceinline__ uint32_t f2tf(float f) {
    uint32_t u;
    asm("cvt.rna.tf32.f32 %0, %1;" : "=r"(u) : "f"(f));
    return u;
}
__device__ __forceinline__ uint2 splitf(float f) {
    uint32_t hi = f2tf(f);
    uint32_t lo = f2tf(f - __uint_as_float(hi));
    return make_uint2(hi, lo);
}

#define MMA_TF32(c, a0, a1, a2, a3, b0, b1)                                   \
    asm volatile("mma.sync.aligned.m16n8k8.row.col.f32.tf32.tf32.f32 "        \
                 "{%0,%1,%2,%3}, {%4,%5,%6,%7}, {%8,%9}, {%0,%1,%2,%3};"      \
                 : "+f"((c)[0]), "+f"((c)[1]), "+f"((c)[2]), "+f"((c)[3])     \
                 : "r"(a0), "r"(a1), "r"(a2), "r"(a3), "r"(b0), "r"(b1))

// smem layout (uint2 units):
//  A stage s: [s*2048 + m*16 + (k ^ ((m&3)<<2))], m in [0,128), k in [0,16)
//  B stage s: [s*2048 + k*128 + (n ^ ((k&3)<<2))], k in [0,16), n in [0,128)
#define GEMM_SMEM_BYTES 65536

__global__ void __launch_bounds__(256, 2)
tf32x3_gemm_kernel(const float* __restrict__ A, const float* __restrict__ Bm,
                   float* __restrict__ C,
                   int M, int Nc, int K, int lda, int ldb, int ldc,
                   long long sAb, long long sAh, long long sBb, long long sBh,
                   long long sCb, long long sCh, int Hh, int transB, float alpha)
{
    extern __shared__ uint2 dynsmem[];
    uint2* As = dynsmem;              // 2 stages * 2048
    uint2* Bs = dynsmem + 4096;       // 2 stages * 2048

    int z = blockIdx.z;
    int b = z / Hh;
    int h = z - b * Hh;
    A  += (long long)b * sAb + (long long)h * sAh;
    Bm += (long long)b * sBb + (long long)h * sBh;
    C  += (long long)b * sCb + (long long)h * sCh;

    int tid  = threadIdx.x;
    int lane = tid & 31, warp = tid >> 5;
    int wr = warp >> 2, wc = warp & 3;       // warp 2x4 layout
    int g = lane >> 2, q = lane & 3;
    int bm0 = blockIdx.y * 128, bn0 = blockIdx.x * 128;

    // per-thread loader coordinates (fixed)
    int a_r[2], a_c0[2];
    int b_i0[2], b_i1[2];
    #pragma unroll
    for (int i = 0; i < 2; i++) {
        int idx = tid + i * 256;
        a_r[i] = idx >> 2; a_c0[i] = (idx & 3) * 4;
        if (!transB) { b_i0[i] = idx >> 5; b_i1[i] = (idx & 31) * 4; } // k, n0
        else         { b_i0[i] = idx >> 2; b_i1[i] = (idx & 3) * 4; }  // n, k40
    }

    float acc[4][4][4];
    #pragma unroll
    for (int i = 0; i < 4; i++)
        #pragma unroll
        for (int j = 0; j < 4; j++)
            #pragma unroll
            for (int e = 0; e < 4; e++) acc[i][j][e] = 0.f;

    float4 rA[2], rB[2];
    const float4 z4 = make_float4(0.f, 0.f, 0.f, 0.f);

    // ---- load tile k0 into registers ----
    auto ldg_tile = [&](int k0) {
        #pragma unroll
        for (int i = 0; i < 2; i++) {
            int gr = bm0 + a_r[i];
            rA[i] = (gr < M) ? *(const float4*)(A + (long long)gr * lda + k0 + a_c0[i]) : z4;
        }
        if (!transB) {
            #pragma unroll
            for (int i = 0; i < 2; i++) {
                int gn = bn0 + b_i1[i];
                rB[i] = (gn < Nc) ? *(const float4*)(Bm + (long long)(k0 + b_i0[i]) * ldb + gn) : z4;
            }
        } else {
            #pragma unroll
            for (int i = 0; i < 2; i++) {
                int gn = bn0 + b_i0[i];
                rB[i] = (gn < Nc) ? *(const float4*)(Bm + (long long)gn * ldb + k0 + b_i1[i]) : z4;
            }
        }
    };

    // ---- convert + store registers into stage s ----
    auto sts_tile = [&](int s) {
        #pragma unroll
        for (int i = 0; i < 2; i++) {
            float vv[4] = {rA[i].x, rA[i].y, rA[i].z, rA[i].w};
            uint2 u[4];
            #pragma unroll
            for (int j = 0; j < 4; j++) u[j] = splitf(vv[j]);
            int r = a_r[i];
            int base = s * 2048 + r * 16 + (a_c0[i] ^ ((r & 3) << 2));
            *(uint4*)&As[base]     = make_uint4(u[0].x, u[0].y, u[1].x, u[1].y);
            *(uint4*)&As[base + 2] = make_uint4(u[2].x, u[2].y, u[3].x, u[3].y);
        }
        if (!transB) {
            #pragma unroll
            for (int i = 0; i < 2; i++) {
                float vv[4] = {rB[i].x, rB[i].y, rB[i].z, rB[i].w};
                uint2 u[4];
                #pragma unroll
                for (int j = 0; j < 4; j++) u[j] = splitf(vv[j]);
                int k = b_i0[i];
                int base = s * 2048 + k * 128 + (b_i1[i] ^ ((k & 3) << 2));
                *(uint4*)&Bs[base]     = make_uint4(u[0].x, u[0].y, u[1].x, u[1].y);
                *(uint4*)&Bs[base + 2] = make_uint4(u[2].x, u[2].y, u[3].x, u[3].y);
            }
        } else {
            #pragma unroll
            for (int i = 0; i < 2; i++) {
                float vv[4] = {rB[i].x, rB[i].y, rB[i].z, rB[i].w};
                int n = b_i0[i], k40 = b_i1[i];
                #pragma unroll
                for (int j = 0; j < 4; j++) {
                    int k = k40 + j;                        // k & 3 == j
                    Bs[s * 2048 + k * 128 + (n ^ (j << 2))] = splitf(vv[j]);
                }
            }
        }
    };

    // ---- compute one ktile from stage s ----
    int sw_a = (g & 3) << 2;
    auto compute_tile = [&](int s) {
        #pragma unroll
        for (int kk = 0; kk < 16; kk += 8) {
            uint2 b0[4], b1[4];
            #pragma unroll
            for (int nt = 0; nt < 4; nt++) {
                int n = wc * 32 + nt * 8 + g;
                int nsw = n ^ (q << 2);
                b0[nt] = Bs[s * 2048 + (kk + q) * 128 + nsw];
                b1[nt] = Bs[s * 2048 + (kk + q + 4) * 128 + nsw];
            }
            #pragma unroll
            for (int mt = 0; mt < 4; mt++) {
                int m = wr * 64 + mt * 16 + g;
                int k1 = (kk + q) ^ sw_a;
                int k2 = (kk + q + 4) ^ sw_a;
                uint2 a0 = As[s * 2048 + m * 16 + k1];
                uint2 a1 = As[s * 2048 + (m + 8) * 16 + k1];
                uint2 a2 = As[s * 2048 + m * 16 + k2];
                uint2 a3 = As[s * 2048 + (m + 8) * 16 + k2];
                #pragma unroll
                for (int nt = 0; nt < 4; nt++)      // hi * lo
                    MMA_TF32(acc[mt][nt], a0.x, a1.x, a2.x, a3.x, b0[nt].y, b1[nt].y);
                #pragma unroll
                for (int nt = 0; nt < 4; nt++)      // lo * hi
                    MMA_TF32(acc[mt][nt], a0.y, a1.y, a2.y, a3.y, b0[nt].x, b1[nt].x);
                #pragma unroll
                for (int nt = 0; nt < 4; nt++)      // hi * hi
                    MMA_TF32(acc[mt][nt], a0.x, a1.x, a2.x, a3.x, b0[nt].x, b1[nt].x);
            }
        }
    };

    // ---- pipelined main loop ----
    ldg_tile(0);
    sts_tile(0);
    __syncthreads();
    int s = 0;
    for (int k0 = 0; k0 < K; k0 += 16) {
        bool more = (k0 + 16) < K;
        if (more) ldg_tile(k0 + 16);
        compute_tile(s);
        if (more) {
            sts_tile(s ^ 1);
            __syncthreads();
        }
        s ^= 1;
    }

    // ---- epilogue: float2 stores ----
    #pragma unroll
    for (int mt = 0; mt < 4; mt++) {
        int r0 = bm0 + wr * 64 + mt * 16 + g;
        #pragma unroll
        for (int nt = 0; nt < 4; nt++) {
            int cix = bn0 + wc * 32 + nt * 8 + q * 2;
            if (cix >= Nc) continue;
            const float* c = acc[mt][nt];
            if (r0 < M)
                *(float2*)(C + (long long)r0 * ldc + cix) =
                    make_float2(alpha * c[0], alpha * c[1]);
            if (r0 + 8 < M)
                *(float2*)(C + (long long)(r0 + 8) * ldc + cix) =
                    make_float2(alpha * c[2], alpha * c[3]);
        }
    }
}

static inline void launch_tgemm(const float* A, const float* Bm, float* C,
                                int M, int Nc, int K, int lda, int ldb, int ldc,
                                long long sAb, long long sAh,
                                long long sBb, long long sBh,
                                long long sCb, long long sCh,
                                int batches, int Hh, int transB, float alpha)
{
    dim3 grid((Nc + 127) / 128, (M + 127) / 128, batches);
    tf32x3_gemm_kernel<<<grid, 256, GEMM_SMEM_BYTES>>>(
        A, Bm, C, M, Nc, K, lda, ldb, ldc,
        sAb, sAh, sBb, sBh, sCb, sCh, Hh, transB, alpha);
}

static inline void launch_tgemm_plain(const float* A, const float* Bm, float* C,
                                      int M, int Nc, int K,
                                      int lda, int ldb, int ldc)
{
    launch_tgemm(A, Bm, C, M, Nc, K, lda, ldb, ldc, 0, 0, 0, 0, 0, 0, 1, 1, 0, 1.f);
}

// ---------------------------------------------------------------------------
// Small fp32 GEMM (kept only for the tiny 8x256x256 qq projection)
// ---------------------------------------------------------------------------
__global__ void __launch_bounds__(256)
fp32_gemm_small_kernel(const float* __restrict__ A, const float* __restrict__ Bm,
                       float* __restrict__ C, int M, int Nc, int K)
{
    int n = blockIdx.x * 256 + threadIdx.x;
    int m = blockIdx.y;
    if (n >= Nc || m >= M) return;
    float s = 0.f;
    for (int k = 0; k < K; k++) s += A[m * K + k] * Bm[k * Nc + n];
    C[m * Nc + n] = s;
}

// ---------------------------------------------------------------------------
// Small fused kernels
// ---------------------------------------------------------------------------
__device__ __forceinline__ float warpSum(float v) {
    #pragma unroll
    for (int o = 16; o; o >>= 1) v += __shfl_down_sync(0xffffffffu, v, o);
    return v;
}

__global__ void posq_kernel(const float* __restrict__ x, const int* __restrict__ mask,
                            float* __restrict__ pq)
{
    int b = blockIdx.x;
    int t = threadIdx.x;
    const float* xb = x + (size_t)b * CN * CD;
    const int* mb = mask + b * CN;
    float s = 0.f;
    int cnt = 0;
    for (int n = 0; n < CN; n++) {
        if (mb[n] == 1) { s += xb[(size_t)n * CD + t]; cnt++; }
    }
    pq[b * CD + t] = s / fmaxf((float)cnt, 1.f);
}

__global__ void possim_kernel(const float* __restrict__ sx, const float* __restrict__ qq,
                              float* __restrict__ out_sim, unsigned char* __restrict__ sel)
{
    int gw = (blockIdx.x * blockDim.x + threadIdx.x) >> 5;
    int lane = threadIdx.x & 31;
    if (gw >= CB * CN) return;
    int b = gw >> 10;
    const float* xr = sx + (size_t)gw * CD;
    const float* qr = qq + b * CD;
    float s = 0.f;
    #pragma unroll
    for (int i = lane; i < CD; i += 32) s += xr[i] * qr[i];
    s = warpSum(s);
    if (lane == 0) {
        float ps = 1.f / (1.f + expf(-s * 0.0625f));
        out_sim[gw] = ps;
        sel[gw] = ps > 0.97f ? 1 : 0;
    }
}

__global__ void bitize_kernel(const float* __restrict__ G,
                              const unsigned char* __restrict__ sel,
                              unsigned* __restrict__ conn)
{
    int row = blockIdx.x;               // b*N + n
    int b = row >> 10;
    int lane = threadIdx.x;
    bool seln = sel[row] != 0;
    const float* Gr = G + (size_t)row * CN;
    const unsigned char* sb = sel + b * CN;
    for (int w = 0; w < 32; w++) {
        int m = w * 32 + lane;
        bool bit = seln && (sb[m] != 0) && (Gr[m] > 0.f);
        unsigned word = __ballot_sync(0xffffffffu, bit);
        if (lane == 0) conn[(size_t)row * 32 + w] = word;
    }
}

__global__ void permW_kernel(const float* __restrict__ W, float* __restrict__ Wc)
{
    int i = blockIdx.x * 256 + threadIdx.x;     // < H*D*D
    int h = i >> 16;
    int r = i & 65535;
    int din = r >> 8;
    int e = r & 255;
    Wc[din * CHD + h * CD + e] = W[i];
}

__global__ void s12_kernel(const float* __restrict__ Wh, const float* __restrict__ a1,
                           const float* __restrict__ a2, float* __restrict__ s1,
                           float* __restrict__ s2)
{
    __shared__ float sa1[CHD], sa2[CHD];
    int t = threadIdx.x;
    for (int i = t; i < CHD; i += 256) { sa1[i] = a1[i]; sa2[i] = a2[i]; }
    __syncthreads();
    int row = blockIdx.x;               // b*N + n
    int w = t >> 5, lane = t & 31;
    const float* wr = Wh + (size_t)row * CHD + w * CD;
    float v1 = 0.f, v2 = 0.f;
    #pragma unroll
    for (int i = lane; i < CD; i += 32) {
        float wv = wr[i];
        v1 += wv * sa1[w * CD + i];
        v2 += wv * sa2[w * CD + i];
    }
    v1 = warpSum(v1);
    v2 = warpSum(v2);
    if (lane == 0) {
        int b = row >> 10, n = row & 1023;
        s1[((size_t)b * CH + w) * CN + n] = v1;
        s2[((size_t)b * CH + w) * CN + n] = v2;
    }
}

__global__ void so12_kernel(const float* __restrict__ Who, const float* __restrict__ ao1,
                            const float* __restrict__ ao2, float* __restrict__ so1,
                            float* __restrict__ so2)
{
    int gw = (blockIdx.x * blockDim.x + threadIdx.x) >> 5;
    int lane = threadIdx.x & 31;
    if (gw >= CB * CN) return;
    const float* wr = Who + (size_t)gw * CD;
    float v1 = 0.f, v2 = 0.f;
    #pragma unroll
    for (int i = lane; i < CD; i += 32) {
        float w = wr[i];
        v1 += w * ao1[i];
        v2 += w * ao2[i];
    }
    v1 = warpSum(v1);
    v2 = warpSum(v2);
    if (lane == 0) { so1[gw] = v1; so2[gw] = v2; }
}

__global__ void rank1_softmax_kernel(const float* __restrict__ s1,
                                     const float* __restrict__ s2,
                                     const unsigned* __restrict__ conn,
                                     float* __restrict__ out, int Hn)
{
    int idx = blockIdx.x;
    int n = idx % CN;
    int bh = idx / CN;
    int b = bh / Hn;
    float s1n = s1[idx];
    const float* s2p = s2 + (size_t)bh * CN;
    const unsigned* cw = conn + ((size_t)b * CN + n) * 32;
    int t = threadIdx.x;

    float lg[4];
    #pragma unroll
    for (int i = 0; i < 4; i++) {
        int m = t + i * 256;
        bool c = (cw[m >> 5] >> (m & 31)) & 1u;
        float z = leaky02(s1n + s2p[m]);
        lg[i] = c ? z : -9.0e15f;
    }

    __shared__ float red[256];
    float mx = fmaxf(fmaxf(lg[0], lg[1]), fmaxf(lg[2], lg[3]));
    red[t] = mx; __syncthreads();
    for (int s = 128; s; s >>= 1) { if (t < s) red[t] = fmaxf(red[t], red[t + s]); __syncthreads(); }
    mx = red[0]; __syncthreads();

    float p[4], sm = 0.f;
    #pragma unroll
    for (int i = 0; i < 4; i++) { p[i] = expf(lg[i] - mx); sm += p[i]; }
    red[t] = sm; __syncthreads();
    for (int s = 128; s; s >>= 1) { if (t < s) red[t] += red[t + s]; __syncthreads(); }
    float inv = 1.f / red[0];

    float* orow = out + (size_t)idx * CN;
    #pragma unroll
    for (int i = 0; i < 4; i++) orow[t + i * 256] = p[i] * inv;
}

__global__ void ca_softmax_kernel(float* __restrict__ logits,
                                  const unsigned char* __restrict__ sel)
{
    int idx = blockIdx.x;
    int b = idx / (CCAH * CN);
    const unsigned char* sb = sel + b * CN;
    float* row = logits + (size_t)idx * CN;
    int t = threadIdx.x;

    float lg[4];
    #pragma unroll
    for (int i = 0; i < 4; i++) {
        int m = t + i * 256;
        lg[i] = sb[m] ? row[m] : -1.0e9f;
    }

    __shared__ float red[256];
    float mx = fmaxf(fmaxf(lg[0], lg[1]), fmaxf(lg[2], lg[3]));
    red[t] = mx; __syncthreads();
    for (int s = 128; s; s >>= 1) { if (t < s) red[t] = fmaxf(red[t], red[t + s]); __syncthreads(); }
    mx = red[0]; __syncthreads();

    float p[4], sm = 0.f;
    #pragma unroll
    for (int i = 0; i < 4; i++) { p[i] = expf(lg[i] - mx); sm += p[i]; }
    red[t] = sm; __syncthreads();
    for (int s = 128; s; s >>= 1) { if (t < s) red[t] += red[t + s]; __syncthreads(); }
    float inv = 1.f / red[0];

    #pragma unroll
    for (int i = 0; i < 4; i++) row[t + i * 256] = p[i] * inv;
}

__global__ void ln_kernel(const float* __restrict__ in, const float* __restrict__ g,
                          const float* __restrict__ bt, float* __restrict__ out)
{
    int row = blockIdx.x;
    int t = threadIdx.x;
    float v = in[(size_t)row * CD + t];
    __shared__ float red[256];
    red[t] = v; __syncthreads();
    for (int s = 128; s; s >>= 1) { if (t < s) red[t] += red[t + s]; __syncthreads(); }
    float mean = red[0] * (1.f / CD);
    __syncthreads();
    float d = v - mean;
    red[t] = d * d; __syncthreads();
    for (int s = 128; s; s >>= 1) { if (t < s) red[t] += red[t + s]; __syncthreads(); }
    float var = red[0] * (1.f / CD);
    out[(size_t)row * CD + t] = d * rsqrtf(var + 1e-5f) * g[t] + bt[t];
}

__global__ void kv_kernel(const float* __restrict__ gout, const float* __restrict__ pe,
                          const unsigned char* __restrict__ sel,
                          const float* __restrict__ g, const float* __restrict__ bt,
                          float* __restrict__ out)
{
    int row = blockIdx.x;
    int n = row & (CN - 1);
    int t = threadIdx.x;
    float v = sel[row] ? (gout[(size_t)row * CD + t] + pe[(size_t)n * CD + t]) : 0.f;
    __shared__ float red[256];
    red[t] = v; __syncthreads();
    for (int s = 128; s; s >>= 1) { if (t < s) red[t] += red[t + s]; __syncthreads(); }
    float mean = red[0] * (1.f / CD);
    __syncthreads();
    float d = v - mean;
    red[t] = d * d; __syncthreads();
    for (int s = 128; s; s >>= 1) { if (t < s) red[t] += red[t + s]; __syncthreads(); }
    float var = red[0] * (1.f / CD);
    out[(size_t)row * CD + t] = d * rsqrtf(var + 1e-5f) * g[t] + bt[t];
}

__global__ void elu_kernel(float* __restrict__ a, size_t n)
{
    size_t i = (size_t)blockIdx.x * 256 + threadIdx.x;
    if (i < n) {
        float v = a[i];
        a[i] = v > 0.f ? v : expm1f(v);
    }
}

__global__ void final_kernel(const float* __restrict__ x, const float* __restrict__ op,
                             const float* __restrict__ gamma, float* __restrict__ out)
{
    size_t i = (size_t)blockIdx.x * 256 + threadIdx.x;
    float g = gamma[i & 255];
    out[i] = x[i] + g * op[i];
}

// ---------------------------------------------------------------------------
// Launch
// ---------------------------------------------------------------------------
#define SYMADDR(p, s) do { void* _t = nullptr; cudaGetSymbolAddress(&_t, s); p = (decltype(p))_t; } while (0)

extern "C" void kernel_launch(void* const* d_in, const int* in_sizes, int n_in,
                              void* d_out, int out_size)
{
    (void)in_sizes; (void)n_in;
    const float* x      = (const float*)d_in[0];
    const int*   mask   = (const int*)d_in[1];
    const float* pe     = (const float*)d_in[2];
    const float* simWx  = (const float*)d_in[3];
    const float* simWq  = (const float*)d_in[4];
    const float* adjW   = (const float*)d_in[5];
    const float* gatW   = (const float*)d_in[6];
    const float* gata1  = (const float*)d_in[7];
    const float* gata2  = (const float*)d_in[8];
    const float* gatWo  = (const float*)d_in[9];
    const float* gatao1 = (const float*)d_in[10];
    const float* gatao2 = (const float*)d_in[11];
    const float* ln3g   = (const float*)d_in[12];
    const float* ln3b   = (const float*)d_in[13];
    const float* ln4g   = (const float*)d_in[14];
    const float* ln4b   = (const float*)d_in[15];
    const float* caWq   = (const float*)d_in[16];
    const float* caWk   = (const float*)d_in[17];
    const float* caWv   = (const float*)d_in[18];
    const float* caWp   = (const float*)d_in[19];
    const float* gamma  = (const float*)d_in[20];
    float* out = (float*)d_out;

    // allow 64 KB dynamic smem for the GEMM (idempotent; capture-legal)
    cudaFuncSetAttribute(tf32x3_gemm_kernel,
                         cudaFuncAttributeMaxDynamicSharedMemorySize,
                         GEMM_SMEM_BYTES);

    float *posq, *sx, *qq, *fa, *G, *Wcat, *Wh, *s1, *s2, *attn, *cat, *Who;
    float *so1, *so2, *gout, *qx, *kv, *q, *k, *v, *o, *op, *simtmp;
    unsigned char* sel;
    unsigned* conn;
    SYMADDR(posq, g_posq);   SYMADDR(sx, g_sx);     SYMADDR(qq, g_qq);
    SYMADDR(sel, g_sel);     SYMADDR(simtmp, g_simtmp);
    SYMADDR(fa, g_fa);       SYMADDR(G, g_G);       SYMADDR(conn, g_conn);
    SYMADDR(Wcat, g_Wcat);   SYMADDR(Wh, g_Wh);
    SYMADDR(s1, g_s1);       SYMADDR(s2, g_s2);     SYMADDR(attn, g_attn);
    SYMADDR(cat, g_cat);     SYMADDR(Who, g_Who);
    SYMADDR(so1, g_so1);     SYMADDR(so2, g_so2);   SYMADDR(gout, g_gout);
    SYMADDR(qx, g_qx);       SYMADDR(kv, g_kv);
    SYMADDR(q, g_q);         SYMADDR(k, g_k);       SYMADDR(v, g_v);
    SYMADDR(o, g_o);         SYMADDR(op, g_op);

    const size_t BND = (size_t)CB * CN * CD;
    float* out_sim = (out_size >= (int)(BND + CB * CN)) ? out + BND : simtmp;

    // --- pos_sim / sel -----------------------------------------------------
    posq_kernel<<<CB, CD>>>(x, mask, posq);
    launch_tgemm_plain(x, simWx, sx, CB * CN, CD, CD, CD, CD, CD);
    fp32_gemm_small_kernel<<<dim3(1, CB), 256>>>(posq, simWq, qq, CB, CD, CD);
    possim_kernel<<<(CB * CN) / 8, 256>>>(sx, qq, out_sim, sel);

    // --- adjacency ----------------------------------------------------------
    launch_tgemm_plain(x, adjW, fa, CB * CN, CD, CD, CD, CD, CD);
    launch_tgemm(fa, fa, G, CN, CN, CD, CD, CD, CN,
                 (long long)CN * CD, 0, (long long)CN * CD, 0,
                 (long long)CN * CN, 0, CB, 1, 1, 1.f);
    bitize_kernel<<<CB * CN, 32>>>(G, sel, conn);

    // --- GAT heads ----------------------------------------------------------
    permW_kernel<<<(CH * CD * CD) / 256, 256>>>(gatW, Wcat);
    launch_tgemm_plain(x, Wcat, Wh, CB * CN, CHD, CD, CD, CHD, CHD);
    s12_kernel<<<CB * CN, 256>>>(Wh, gata1, gata2, s1, s2);
    rank1_softmax_kernel<<<CB * CH * CN, 256>>>(s1, s2, conn, attn, CH);
    launch_tgemm(attn, Wh, cat, CN, CD, CN, CN, CHD, CHD,
                 (long long)CH * CN * CN, (long long)CN * CN,
                 (long long)CN * CHD, CD,
                 (long long)CN * CHD, CD, CB * CH, CH, 0, 1.f);
    elu_kernel<<<(unsigned)(((size_t)CB * CN * CHD) / 256), 256>>>(cat, (size_t)CB * CN * CHD);

    // --- GAT output layer ----------------------------------------------------
    launch_tgemm_plain(cat, gatWo, Who, CB * CN, CD, CHD, CHD, CD, CD);
    so12_kernel<<<(CB * CN) / 8, 256>>>(Who, gatao1, gatao2, so1, so2);
    rank1_softmax_kernel<<<CB * CN, 256>>>(so1, so2, conn, G, 1);
    launch_tgemm(G, Who, gout, CN, CD, CN, CN, CD, CD,
                 (long long)CN * CN, 0, (long long)CN * CD, 0,
                 (long long)CN * CD, 0, CB, 1, 0, 1.f);
    elu_kernel<<<(unsigned)(BND / 256), 256>>>(gout, BND);

    // --- CrossAttention -------------------------------------------------------
    ln_kernel<<<CB * CN, 256>>>(x, ln3g, ln3b, qx);
    kv_kernel<<<CB * CN, 256>>>(gout, pe, sel, ln4g, ln4b, kv);
    launch_tgemm_plain(qx, caWq, q, CB * CN, CD, CD, CD, CD, CD);
    launch_tgemm_plain(kv, caWk, k, CB * CN, CD, CD, CD, CD, CD);
    launch_tgemm_plain(kv, caWv, v, CB * CN, CD, CD, CD, CD, CD);
    launch_tgemm(q, k, attn, CN, CN, CDH, CD, CD, CN,
                 (long long)CN * CD, CDH, (long long)CN * CD, CDH,
                 (long long)CCAH * CN * CN, (long long)CN * CN,
                 CB * CCAH, CCAH, 1, 0.125f);
    ca_softmax_kernel<<<CB * CCAH * CN, 256>>>(attn, sel);
    launch_tgemm(attn, v, o, CN, CDH, CN, CN, CD, CD,
                 (long long)CCAH * CN * CN, (long long)CN * CN,
                 (long long)CN * CD, CDH,
                 (long long)CN * CD, CDH, CB * CCAH, CCAH, 0, 1.f);
    launch_tgemm_plain(o, caWp, op, CB * CN, CD, CD, CD, CD, CD);

    final_kernel<<<(unsigned)(BND / 256), 256>>>(x, op, gamma, out);
}